// round 6
// baseline (speedup 1.0000x reference)
#include <cuda_runtime.h>
#include <cuda_bf16.h>

#define MAX_NODES 50000
#define CH 128          // IN_CH == HID_CH == 128
#define OUTC 64

// ---- device scratch (no allocations; referenced directly from device code) ----
__device__ float g_H[MAX_NODES * CH];       // x @ W1
__device__ float g_hidden[MAX_NODES * CH];  // agg1 -> relu(hidden+b1)
__device__ float g_agg2[MAX_NODES * CH];    // A_hat @ hidden
__device__ int   g_deg[MAX_NODES];
__device__ float g_dinv[MAX_NODES];
__device__ int   g_is64;                    // edge_index dtype flag

// ---------------- dtype detect: int64 edge buffer has zero high words ----------------
__global__ void k_detect(const int* __restrict__ ei32) {
    if (threadIdx.x == 0 && blockIdx.x == 0) {
        int allzero = 1;
        for (int i = 1; i < 512; i += 2)
            if (ei32[i] != 0) { allzero = 0; break; }
        g_is64 = allzero;
    }
}

__device__ __forceinline__ int edge_at(const void* ei, int i) {
    if (g_is64) return (int)((const long long*)ei)[i];
    return ((const int*)ei)[i];
}

// ---------------- degree / norm ----------------
__global__ void k_zero_deg(int n) {
    int i = blockIdx.x * blockDim.x + threadIdx.x;
    if (i < n) g_deg[i] = 0;
}

__global__ void k_count(const void* __restrict__ ei, int nE) {
    int e = blockIdx.x * blockDim.x + threadIdx.x;
    if (e < nE) {
        int c = edge_at(ei, nE + e);   // target node
        atomicAdd(&g_deg[c], 1);
    }
}

__global__ void k_dinv(int n) {
    int i = blockIdx.x * blockDim.x + threadIdx.x;
    if (i < n) g_dinv[i] = rsqrtf((float)(g_deg[i] + 1));  // +1 self loop
}

// ---------------- GEMM layer 1: g_H = x[n,128] @ W1[128,128] ----------------
// Block: 64 rows x 128 cols, K chunked by 32. smem = 16KB + 8KB = 24KB.
__global__ __launch_bounds__(256) void k_gemm1(const float* __restrict__ X,
                                               const float* __restrict__ W, int n) {
    __shared__ float Ws[32 * 128];   // Ws[k][c]
    __shared__ float Xs[64 * 32];    // Xs[r][k]
    int tid  = threadIdx.x;
    int w    = tid >> 5;
    int lane = tid & 31;
    int c4   = lane * 4;
    int row0 = blockIdx.x * 64;

    float4 acc[8];
#pragma unroll
    for (int i = 0; i < 8; i++) acc[i] = make_float4(0.f, 0.f, 0.f, 0.f);

    for (int kc = 0; kc < CH; kc += 32) {
        __syncthreads();
#pragma unroll
        for (int j = 0; j < 4; j++) {
            int idx4 = tid + j * 256;
            int k = idx4 >> 5, c = (idx4 & 31) * 4;
            *(float4*)&Ws[k * 128 + c] = *(const float4*)&W[(size_t)(kc + k) * 128 + c];
        }
#pragma unroll
        for (int j = 0; j < 2; j++) {
            int idx4 = tid + j * 256;
            int r = idx4 >> 3, k = (idx4 & 7) * 4;
            float4 v = make_float4(0.f, 0.f, 0.f, 0.f);
            if (row0 + r < n) v = *(const float4*)&X[(size_t)(row0 + r) * 128 + kc + k];
            *(float4*)&Xs[r * 32 + k] = v;
        }
        __syncthreads();

#pragma unroll 8
        for (int k = 0; k < 32; k++) {
            float4 wv = *(float4*)&Ws[k * 128 + c4];
#pragma unroll
            for (int i = 0; i < 8; i++) {
                float xv = Xs[(w * 8 + i) * 32 + k];
                acc[i].x += xv * wv.x; acc[i].y += xv * wv.y;
                acc[i].z += xv * wv.z; acc[i].w += xv * wv.w;
            }
        }
    }
#pragma unroll
    for (int i = 0; i < 8; i++) {
        int row = row0 + w * 8 + i;
        if (row < n) *(float4*)&g_H[(size_t)row * 128 + c4] = acc[i];
    }
}

// ---------------- final GEMM: out = relu(g_agg2 @ [W2|W3] + [b2|b3]) ----------------
__global__ __launch_bounds__(256) void k_gemm2(const float* __restrict__ W2,
                                               const float* __restrict__ W3,
                                               const float* __restrict__ b2,
                                               const float* __restrict__ b3,
                                               float* __restrict__ out, int n) {
    __shared__ float Ws[32 * 128];
    __shared__ float Xs[64 * 32];
    __shared__ float bs[128];
    int tid  = threadIdx.x;
    int w    = tid >> 5;
    int lane = tid & 31;
    int c4   = lane * 4;
    int row0 = blockIdx.x * 64;

    if (tid < OUTC) { bs[tid] = b2[tid]; bs[OUTC + tid] = b3[tid]; }

    float4 acc[8];
#pragma unroll
    for (int i = 0; i < 8; i++) acc[i] = make_float4(0.f, 0.f, 0.f, 0.f);

    for (int kc = 0; kc < CH; kc += 32) {
        __syncthreads();
#pragma unroll
        for (int j = 0; j < 4; j++) {
            int idx4 = tid + j * 256;
            int k = idx4 >> 5, c = (idx4 & 31) * 4;
            float4 v;
            if (c < OUTC) v = *(const float4*)&W2[(size_t)(kc + k) * OUTC + c];
            else          v = *(const float4*)&W3[(size_t)(kc + k) * OUTC + (c - OUTC)];
            *(float4*)&Ws[k * 128 + c] = v;
        }
#pragma unroll
        for (int j = 0; j < 2; j++) {
            int idx4 = tid + j * 256;
            int r = idx4 >> 3, k = (idx4 & 7) * 4;
            float4 v = make_float4(0.f, 0.f, 0.f, 0.f);
            if (row0 + r < n) v = *(const float4*)&g_agg2[(size_t)(row0 + r) * 128 + kc + k];
            *(float4*)&Xs[r * 32 + k] = v;
        }
        __syncthreads();

#pragma unroll 8
        for (int k = 0; k < 32; k++) {
            float4 wv = *(float4*)&Ws[k * 128 + c4];
#pragma unroll
            for (int i = 0; i < 8; i++) {
                float xv = Xs[(w * 8 + i) * 32 + k];
                acc[i].x += xv * wv.x; acc[i].y += xv * wv.y;
                acc[i].z += xv * wv.z; acc[i].w += xv * wv.w;
            }
        }
    }

    float4 bv = *(float4*)&bs[c4];
    size_t half = (size_t)n * OUTC;
#pragma unroll
    for (int i = 0; i < 8; i++) {
        int row = row0 + w * 8 + i;
        if (row < n) {
            float4 v;
            v.x = fmaxf(acc[i].x + bv.x, 0.f);
            v.y = fmaxf(acc[i].y + bv.y, 0.f);
            v.z = fmaxf(acc[i].z + bv.z, 0.f);
            v.w = fmaxf(acc[i].w + bv.w, 0.f);
            if (c4 < OUTC) *(float4*)&out[(size_t)row * OUTC + c4] = v;
            else           *(float4*)&out[half + (size_t)row * OUTC + (c4 - OUTC)] = v;
        }
    }
}

// ---------------- self-loop init: g_hidden = g_H * dinv[node]^2 ----------------
__global__ void k_selfinit(int n) {
    int i = blockIdx.x * blockDim.x + threadIdx.x;   // float4 index
    if (i < n * 32) {
        int node = i >> 5;
        float d = g_dinv[node];
        float s = d * d;
        float4 v = ((const float4*)g_H)[i];
        v.x *= s; v.y *= s; v.z *= s; v.w *= s;
        ((float4*)g_hidden)[i] = v;
    }
}

// ---------------- edge scatter: A[col] += H[row] * dinv[row]*dinv[col] ----------------
// One warp per edge; vectorized L2 reductions (red.global.add.v4.f32).
template <int PASS>
__global__ __launch_bounds__(256) void k_scatter(const void* __restrict__ ei, int nE) {
    int gt = blockIdx.x * blockDim.x + threadIdx.x;
    int e = gt >> 5;
    int lane = gt & 31;
    if (e >= nE) return;
    const float* H = (PASS == 0) ? g_H : g_hidden;
    float*       A = (PASS == 0) ? g_hidden : g_agg2;
    int r = edge_at(ei, e);
    int c = edge_at(ei, nE + e);
    float nrm = g_dinv[r] * g_dinv[c];
    float4 v = ((const float4*)(H + (size_t)r * CH))[lane];
    v.x *= nrm; v.y *= nrm; v.z *= nrm; v.w *= nrm;
    float* d = A + (size_t)c * CH + lane * 4;
    asm volatile("red.global.add.v4.f32 [%0], {%1, %2, %3, %4};"
                 :: "l"(d), "f"(v.x), "f"(v.y), "f"(v.z), "f"(v.w) : "memory");
}

// ---------------- relu(hidden + b1) in place; g_agg2 = relu * dinv^2 ----------------
__global__ void k_relu_init2(const float* __restrict__ b1, int n) {
    int i = blockIdx.x * blockDim.x + threadIdx.x;   // float4 index
    if (i < n * 32) {
        int node = i >> 5;
        int ch4 = (i & 31) * 4;
        float4 bv = *(const float4*)&b1[ch4];
        float4 v = ((const float4*)g_hidden)[i];
        v.x = fmaxf(v.x + bv.x, 0.f); v.y = fmaxf(v.y + bv.y, 0.f);
        v.z = fmaxf(v.z + bv.z, 0.f); v.w = fmaxf(v.w + bv.w, 0.f);
        ((float4*)g_hidden)[i] = v;
        float dd = g_dinv[node]; dd *= dd;
        float4 a = make_float4(v.x * dd, v.y * dd, v.z * dd, v.w * dd);
        ((float4*)g_agg2)[i] = a;
    }
}

extern "C" void kernel_launch(void* const* d_in, const int* in_sizes, int n_in,
                              void* d_out, int out_size) {
    const float* x  = (const float*)d_in[0];
    const void*  ei = d_in[1];
    const float* W1 = (const float*)d_in[2];
    const float* b1 = (const float*)d_in[3];
    const float* W2 = (const float*)d_in[4];
    const float* b2 = (const float*)d_in[5];
    const float* W3 = (const float*)d_in[6];
    const float* b3 = (const float*)d_in[7];
    float* out = (float*)d_out;

    int nN = in_sizes[0] / CH;   // 50000
    int nE = in_sizes[1] / 2;    // 800000

    int tb = 256;
    k_detect  <<<1, 32>>>((const int*)ei);
    k_zero_deg<<<(nN + tb - 1) / tb, tb>>>(nN);
    k_count   <<<(nE + tb - 1) / tb, tb>>>(ei, nE);
    k_dinv    <<<(nN + tb - 1) / tb, tb>>>(nN);

    // layer 1: H = x @ W1
    k_gemm1<<<(nN + 63) / 64, 256>>>(x, W1, nN);
    // hidden = dinv^2 * H (self loop) then scatter-add over edges
    k_selfinit<<<(nN * 32 + tb - 1) / tb, tb>>>(nN);
    k_scatter<0><<<(nE * 32 + tb - 1) / tb, tb>>>(ei, nE);
    // hidden = relu(hidden + b1); agg2 = dinv^2 * hidden
    k_relu_init2<<<(nN * 32 + tb - 1) / tb, tb>>>(b1, nN);
    // agg2 += edges over hidden
    k_scatter<1><<<(nE * 32 + tb - 1) / tb, tb>>>(ei, nE);
    // out = relu(agg2 @ [W2|W3] + [b2|b3]) -> (x1, x2)
    k_gemm2<<<(nN + 63) / 64, 256>>>(W2, W3, b2, b3, out, nN);
}

// round 7
// speedup vs baseline: 1.2606x; 1.2606x over previous
#include <cuda_runtime.h>
#include <cuda_bf16.h>

#define MAX_NODES 50000
#define MAX_EDGES 800000
#define CH 128
#define OUTC 64

// ---- device scratch ----
__device__ float g_H[MAX_NODES * CH];       // x @ W1
__device__ float g_hidden[MAX_NODES * CH];  // relu(A_hat@H + b1)
__device__ float g_agg2[MAX_NODES * CH];    // A_hat @ hidden
__device__ int   g_deg[MAX_NODES];
__device__ float g_dinv[MAX_NODES];
__device__ int   g_is64;
// CSR by target node
__device__ int   g_ptr[MAX_NODES + 1];
__device__ int   g_cursor[MAX_NODES];
__device__ int   g_src[MAX_EDGES];
__device__ float g_nrm[MAX_EDGES];
__device__ int   g_bsum[64];
__device__ int   g_boff[64];

#define FMA_F32X2(acc, a, b) \
    asm("fma.rn.f32x2 %0, %1, %2, %0;" : "+l"(acc) : "l"(a), "l"(b))
#define PACK_DUP(d, f) \
    asm("mov.b64 %0, {%1, %1};" : "=l"(d) : "f"(f))
#define UNPACK2(lo, hi, p) \
    asm("mov.b64 {%0, %1}, %2;" : "=f"(lo), "=f"(hi) : "l"(p))

// ---------------- dtype detect ----------------
__global__ void k_detect(const int* __restrict__ ei32) {
    if (threadIdx.x == 0) {
        int allzero = 1;
        for (int i = 1; i < 512; i += 2)
            if (ei32[i] != 0) { allzero = 0; break; }
        g_is64 = allzero;
    }
}

__device__ __forceinline__ int edge_at(const void* ei, int i) {
    if (g_is64) return (int)((const long long*)ei)[i];
    return ((const int*)ei)[i];
}

// ---------------- degree / norm ----------------
__global__ void k_zero_deg(int n) {
    int i = blockIdx.x * blockDim.x + threadIdx.x;
    if (i < n) g_deg[i] = 0;
}

__global__ void k_count(const void* __restrict__ ei, int nE) {
    int e = blockIdx.x * blockDim.x + threadIdx.x;
    if (e < nE) atomicAdd(&g_deg[edge_at(ei, nE + e)], 1);
}

__global__ void k_dinv(int n) {
    int i = blockIdx.x * blockDim.x + threadIdx.x;
    if (i < n) g_dinv[i] = rsqrtf((float)(g_deg[i] + 1));   // +1 self loop
}

// ---------------- CSR build: 3-kernel exclusive scan + fill ----------------
__global__ __launch_bounds__(1024) void k_scan1(int n) {
    __shared__ int wsum[32];
    int i = blockIdx.x * 1024 + threadIdx.x;
    int lane = threadIdx.x & 31, wid = threadIdx.x >> 5;
    int s = (i < n) ? g_deg[i] : 0;
#pragma unroll
    for (int o = 1; o < 32; o <<= 1) {
        int t = __shfl_up_sync(~0u, s, o);
        if (lane >= o) s += t;
    }
    if (lane == 31) wsum[wid] = s;
    __syncthreads();
    if (wid == 0) {
        int ws = wsum[lane];
#pragma unroll
        for (int o = 1; o < 32; o <<= 1) {
            int t = __shfl_up_sync(~0u, ws, o);
            if (lane >= o) ws += t;
        }
        wsum[lane] = ws;
    }
    __syncthreads();
    int incl = s + (wid > 0 ? wsum[wid - 1] : 0);
    if (i < n) g_ptr[i + 1] = incl;
    if (threadIdx.x == 1023) g_bsum[blockIdx.x] = incl;
}

__global__ void k_scan2(int nb) {
    if (threadIdx.x == 0) {
        int run = 0;
        for (int b = 0; b < nb; b++) { g_boff[b] = run; run += g_bsum[b]; }
    }
}

__global__ void k_scan3(int n) {
    int i = blockIdx.x * blockDim.x + threadIdx.x;
    if (i < n) {
        int p1 = g_ptr[i + 1] + g_boff[i >> 10];
        g_ptr[i + 1] = p1;
        g_cursor[i] = p1 - g_deg[i];
    }
    if (i == 0) g_ptr[0] = 0;
}

__global__ void k_fill(const void* __restrict__ ei, int nE) {
    int e = blockIdx.x * blockDim.x + threadIdx.x;
    if (e < nE) {
        int r = edge_at(ei, e);
        int c = edge_at(ei, nE + e);
        int pos = atomicAdd(&g_cursor[c], 1);
        g_src[pos] = r;
        g_nrm[pos] = g_dinv[r] * g_dinv[c];
    }
}

// ---------------- GEMM layer 1: g_H = x[n,128] @ W1[128,128] (f32x2) ----------------
// Block: 64 rows x 128 cols; thread: 4 rows x 8 cols. rowg = tid>>4, colg = tid&15.
__global__ __launch_bounds__(256) void k_gemm1(const float* __restrict__ X,
                                               const float* __restrict__ W, int n) {
    __shared__ float Ws[32 * 128];   // [k][c]
    __shared__ float Xs[64 * 32];    // [r][k]
    int tid  = threadIdx.x;
    int r0   = (tid >> 4) * 4;
    int c0   = (tid & 15) * 8;
    int row0 = blockIdx.x * 64;

    unsigned long long acc[4][4];
#pragma unroll
    for (int i = 0; i < 4; i++)
#pragma unroll
        for (int j = 0; j < 4; j++) acc[i][j] = 0ull;

    for (int kc = 0; kc < CH; kc += 32) {
        __syncthreads();
#pragma unroll
        for (int j = 0; j < 4; j++) {
            int idx4 = tid + j * 256;
            int k = idx4 >> 5, c = (idx4 & 31) * 4;
            *(float4*)&Ws[k * 128 + c] = *(const float4*)&W[(size_t)(kc + k) * 128 + c];
        }
#pragma unroll
        for (int j = 0; j < 2; j++) {
            int idx4 = tid + j * 256;
            int r = idx4 >> 3, k = (idx4 & 7) * 4;
            float4 v = make_float4(0.f, 0.f, 0.f, 0.f);
            if (row0 + r < n) v = *(const float4*)&X[(size_t)(row0 + r) * 128 + kc + k];
            *(float4*)&Xs[r * 32 + k] = v;
        }
        __syncthreads();

#pragma unroll 8
        for (int k = 0; k < 32; k++) {
            ulonglong2 wa = *(const ulonglong2*)&Ws[k * 128 + c0];
            ulonglong2 wb = *(const ulonglong2*)&Ws[k * 128 + c0 + 4];
#pragma unroll
            for (int i = 0; i < 4; i++) {
                float xf = Xs[(r0 + i) * 32 + k];
                unsigned long long xp; PACK_DUP(xp, xf);
                FMA_F32X2(acc[i][0], xp, wa.x);
                FMA_F32X2(acc[i][1], xp, wa.y);
                FMA_F32X2(acc[i][2], xp, wb.x);
                FMA_F32X2(acc[i][3], xp, wb.y);
            }
        }
    }
#pragma unroll
    for (int i = 0; i < 4; i++) {
        int row = row0 + r0 + i;
        if (row < n) {
            float4 v0, v1;
            UNPACK2(v0.x, v0.y, acc[i][0]); UNPACK2(v0.z, v0.w, acc[i][1]);
            UNPACK2(v1.x, v1.y, acc[i][2]); UNPACK2(v1.z, v1.w, acc[i][3]);
            *(float4*)&g_H[(size_t)row * 128 + c0]     = v0;
            *(float4*)&g_H[(size_t)row * 128 + c0 + 4] = v1;
        }
    }
}

// ---------------- final GEMM: out = relu(g_agg2 @ [W2|W3] + [b2|b3]) ----------------
__global__ __launch_bounds__(256) void k_gemm2(const float* __restrict__ W2,
                                               const float* __restrict__ W3,
                                               const float* __restrict__ b2,
                                               const float* __restrict__ b3,
                                               float* __restrict__ out, int n) {
    __shared__ float Ws[32 * 128];
    __shared__ float Xs[64 * 32];
    __shared__ float bs[128];
    int tid  = threadIdx.x;
    int r0   = (tid >> 4) * 4;
    int c0   = (tid & 15) * 8;
    int row0 = blockIdx.x * 64;

    if (tid < OUTC) { bs[tid] = b2[tid]; bs[OUTC + tid] = b3[tid]; }

    unsigned long long acc[4][4];
#pragma unroll
    for (int i = 0; i < 4; i++)
#pragma unroll
        for (int j = 0; j < 4; j++) acc[i][j] = 0ull;

    for (int kc = 0; kc < CH; kc += 32) {
        __syncthreads();
#pragma unroll
        for (int j = 0; j < 4; j++) {
            int idx4 = tid + j * 256;
            int k = idx4 >> 5, c = (idx4 & 31) * 4;
            float4 v;
            if (c < OUTC) v = *(const float4*)&W2[(size_t)(kc + k) * OUTC + c];
            else          v = *(const float4*)&W3[(size_t)(kc + k) * OUTC + (c - OUTC)];
            *(float4*)&Ws[k * 128 + c] = v;
        }
#pragma unroll
        for (int j = 0; j < 2; j++) {
            int idx4 = tid + j * 256;
            int r = idx4 >> 3, k = (idx4 & 7) * 4;
            float4 v = make_float4(0.f, 0.f, 0.f, 0.f);
            if (row0 + r < n) v = *(const float4*)&g_agg2[(size_t)(row0 + r) * 128 + kc + k];
            *(float4*)&Xs[r * 32 + k] = v;
        }
        __syncthreads();

#pragma unroll 8
        for (int k = 0; k < 32; k++) {
            ulonglong2 wa = *(const ulonglong2*)&Ws[k * 128 + c0];
            ulonglong2 wb = *(const ulonglong2*)&Ws[k * 128 + c0 + 4];
#pragma unroll
            for (int i = 0; i < 4; i++) {
                float xf = Xs[(r0 + i) * 32 + k];
                unsigned long long xp; PACK_DUP(xp, xf);
                FMA_F32X2(acc[i][0], xp, wa.x);
                FMA_F32X2(acc[i][1], xp, wa.y);
                FMA_F32X2(acc[i][2], xp, wb.x);
                FMA_F32X2(acc[i][3], xp, wb.y);
            }
        }
    }

    float4 bv0 = *(float4*)&bs[c0];
    float4 bv1 = *(float4*)&bs[c0 + 4];
    size_t half = (size_t)n * OUTC;
#pragma unroll
    for (int i = 0; i < 4; i++) {
        int row = row0 + r0 + i;
        if (row < n) {
            float4 v0, v1;
            UNPACK2(v0.x, v0.y, acc[i][0]); UNPACK2(v0.z, v0.w, acc[i][1]);
            UNPACK2(v1.x, v1.y, acc[i][2]); UNPACK2(v1.z, v1.w, acc[i][3]);
            v0.x = fmaxf(v0.x + bv0.x, 0.f); v0.y = fmaxf(v0.y + bv0.y, 0.f);
            v0.z = fmaxf(v0.z + bv0.z, 0.f); v0.w = fmaxf(v0.w + bv0.w, 0.f);
            v1.x = fmaxf(v1.x + bv1.x, 0.f); v1.y = fmaxf(v1.y + bv1.y, 0.f);
            v1.z = fmaxf(v1.z + bv1.z, 0.f); v1.w = fmaxf(v1.w + bv1.w, 0.f);
            float* base = (c0 < OUTC) ? &out[(size_t)row * OUTC + c0]
                                      : &out[half + (size_t)row * OUTC + (c0 - OUTC)];
            *(float4*)base       = v0;
            *(float4*)(base + 4) = v1;
        }
    }
}

// ---------------- CSR gather: one warp per target node ----------------
// PASS 0: in g_H,  out g_hidden = relu(sum + b1)
// PASS 1: in g_hidden, out g_agg2 = sum
template <int PASS>
__global__ __launch_bounds__(256) void k_gather(const float* __restrict__ b1, int n) {
    int gt = blockIdx.x * blockDim.x + threadIdx.x;
    int node = gt >> 5, lane = gt & 31;
    if (node >= n) return;
    const float* __restrict__ H = (PASS == 0) ? g_H : g_hidden;
    int beg = g_ptr[node], end = g_ptr[node + 1];
    float dn = g_dinv[node];
    float s0 = dn * dn;
    float4 acc = ((const float4*)(H + (size_t)node * CH))[lane];   // self loop
    acc.x *= s0; acc.y *= s0; acc.z *= s0; acc.w *= s0;

    int j = beg;
    for (; j + 1 < end; j += 2) {
        int s1 = g_src[j], s2 = g_src[j + 1];
        float w1 = g_nrm[j], w2 = g_nrm[j + 1];
        float4 v1 = ((const float4*)(H + (size_t)s1 * CH))[lane];
        float4 v2 = ((const float4*)(H + (size_t)s2 * CH))[lane];
        acc.x += v1.x * w1 + v2.x * w2;
        acc.y += v1.y * w1 + v2.y * w2;
        acc.z += v1.z * w1 + v2.z * w2;
        acc.w += v1.w * w1 + v2.w * w2;
    }
    if (j < end) {
        int s1 = g_src[j];
        float w1 = g_nrm[j];
        float4 v1 = ((const float4*)(H + (size_t)s1 * CH))[lane];
        acc.x += v1.x * w1; acc.y += v1.y * w1;
        acc.z += v1.z * w1; acc.w += v1.w * w1;
    }

    if (PASS == 0) {
        float4 bv = *(const float4*)&b1[lane * 4];
        acc.x = fmaxf(acc.x + bv.x, 0.f); acc.y = fmaxf(acc.y + bv.y, 0.f);
        acc.z = fmaxf(acc.z + bv.z, 0.f); acc.w = fmaxf(acc.w + bv.w, 0.f);
        ((float4*)(g_hidden + (size_t)node * CH))[lane] = acc;
    } else {
        ((float4*)(g_agg2 + (size_t)node * CH))[lane] = acc;
    }
}

extern "C" void kernel_launch(void* const* d_in, const int* in_sizes, int n_in,
                              void* d_out, int out_size) {
    const float* x  = (const float*)d_in[0];
    const void*  ei = d_in[1];
    const float* W1 = (const float*)d_in[2];
    const float* b1 = (const float*)d_in[3];
    const float* W2 = (const float*)d_in[4];
    const float* b2 = (const float*)d_in[5];
    const float* W3 = (const float*)d_in[6];
    const float* b3 = (const float*)d_in[7];
    float* out = (float*)d_out;

    int nN = in_sizes[0] / CH;   // 50000
    int nE = in_sizes[1] / 2;    // 800000
    int tb = 256;
    int nb = (nN + 1023) / 1024;

    k_detect  <<<1, 32>>>((const int*)ei);
    k_zero_deg<<<(nN + tb - 1) / tb, tb>>>(nN);
    k_count   <<<(nE + tb - 1) / tb, tb>>>(ei, nE);
    k_dinv    <<<(nN + tb - 1) / tb, tb>>>(nN);
    // CSR build
    k_scan1<<<nb, 1024>>>(nN);
    k_scan2<<<1, 32>>>(nb);
    k_scan3<<<(nN + tb - 1) / tb, tb>>>(nN);
    k_fill <<<(nE + tb - 1) / tb, tb>>>(ei, nE);

    // layer 1: H = x @ W1
    k_gemm1<<<(nN + 63) / 64, 256>>>(x, W1, nN);
    // hidden = relu(A_hat @ H + b1)   (gather, no atomics)
    k_gather<0><<<(nN * 32 + tb - 1) / tb, tb>>>(b1, nN);
    // agg2 = A_hat @ hidden
    k_gather<1><<<(nN * 32 + tb - 1) / tb, tb>>>(b1, nN);
    // out = relu(agg2 @ [W2|W3] + [b2|b3]) -> (x1, x2)
    k_gemm2<<<(nN + 63) / 64, 256>>>(W2, W3, b2, b3, out, nN);
}

// round 9
// speedup vs baseline: 1.3389x; 1.0620x over previous
#include <cuda_runtime.h>
#include <cuda_bf16.h>

#define MAX_NODES 50000
#define MAX_EDGES 800000
#define CH 128
#define OUTC 64

// ---- device scratch ----
__device__ float g_H[MAX_NODES * CH];       // x @ W1
__device__ float g_hidden[MAX_NODES * CH];  // relu(A_hat@H + b1)
__device__ int   g_deg[MAX_NODES];
__device__ float g_dinv[MAX_NODES];
// CSR by target node; edge payload packed as {src:int, nrm:float}
__device__ int   g_ptr[MAX_NODES + 1];
__device__ int   g_cursor[MAX_NODES];
__device__ int2  g_edge[MAX_EDGES];
__device__ int   g_bsum[64];
__device__ int   g_boff[64];

#define FMA_F32X2(acc, a, b) \
    asm("fma.rn.f32x2 %0, %1, %2, %0;" : "+l"(acc) : "l"(a), "l"(b))
#define PACK_DUP(d, f) \
    asm("mov.b64 %0, {%1, %1};" : "=l"(d) : "f"(f))
#define UNPACK2(lo, hi, p) \
    asm("mov.b64 {%0, %1}, %2;" : "=f"(lo), "=f"(hi) : "l"(p))

// Per-block int64-vs-int32 edge dtype detection: odd 32-bit words of an int64
// buffer with values < 50000 are all zero. Reads words 1,3,...,63 (L2-hot).
__device__ __forceinline__ int detect_is64(const void* ei) {
    __shared__ int s_is64;
    if (threadIdx.x < 32) {
        int w = ((const int*)ei)[2 * threadIdx.x + 1];
        unsigned m = __ballot_sync(~0u, w == 0);
        if (threadIdx.x == 0) s_is64 = (m == ~0u);
    }
    __syncthreads();
    return s_is64;
}

__device__ __forceinline__ int edge_at(const void* ei, int i, int is64) {
    if (is64) return (int)((const long long*)ei)[i];
    return ((const int*)ei)[i];
}

// ---------------- degree ----------------
__global__ void k_zero(int n) {
    int i = blockIdx.x * blockDim.x + threadIdx.x;
    if (i < n) g_deg[i] = 0;
}

__global__ void k_count(const void* __restrict__ ei, int nE) {
    int is64 = detect_is64(ei);
    int e = blockIdx.x * blockDim.x + threadIdx.x;
    if (e < nE) atomicAdd(&g_deg[edge_at(ei, nE + e, is64)], 1);
}

// ---------------- CSR build: scan (+dinv) + fill ----------------
__global__ __launch_bounds__(1024) void k_scan1(int n) {
    __shared__ int wsum[32];
    int i = blockIdx.x * 1024 + threadIdx.x;
    int lane = threadIdx.x & 31, wid = threadIdx.x >> 5;
    int d = (i < n) ? g_deg[i] : 0;
    if (i < n) g_dinv[i] = rsqrtf((float)(d + 1));   // +1 self loop (fused k_dinv)
    int s = d;
#pragma unroll
    for (int o = 1; o < 32; o <<= 1) {
        int t = __shfl_up_sync(~0u, s, o);
        if (lane >= o) s += t;
    }
    if (lane == 31) wsum[wid] = s;
    __syncthreads();
    if (wid == 0) {
        int ws = wsum[lane];
#pragma unroll
        for (int o = 1; o < 32; o <<= 1) {
            int t = __shfl_up_sync(~0u, ws, o);
            if (lane >= o) ws += t;
        }
        wsum[lane] = ws;
    }
    __syncthreads();
    int incl = s + (wid > 0 ? wsum[wid - 1] : 0);
    if (i < n) g_ptr[i + 1] = incl;
    if (threadIdx.x == 1023) g_bsum[blockIdx.x] = incl;
}

__global__ void k_scan2(int nb) {
    if (threadIdx.x == 0) {
        int run = 0;
        for (int b = 0; b < nb; b++) { g_boff[b] = run; run += g_bsum[b]; }
    }
}

__global__ void k_scan3(int n) {
    int i = blockIdx.x * blockDim.x + threadIdx.x;
    if (i < n) {
        int p1 = g_ptr[i + 1] + g_boff[i >> 10];
        g_ptr[i + 1] = p1;
        g_cursor[i] = p1 - g_deg[i];
    }
    if (i == 0) g_ptr[0] = 0;
}

__global__ void k_fill(const void* __restrict__ ei, int nE) {
    int is64 = detect_is64(ei);
    int e = blockIdx.x * blockDim.x + threadIdx.x;
    if (e < nE) {
        int r = edge_at(ei, e, is64);
        int c = edge_at(ei, nE + e, is64);
        int pos = atomicAdd(&g_cursor[c], 1);
        float nrm = g_dinv[r] * g_dinv[c];
        g_edge[pos] = make_int2(r, __float_as_int(nrm));
    }
}

// ---------------- GEMM layer 1: g_H = x[n,128] @ W1[128,128] (f32x2) ----------------
__global__ __launch_bounds__(256) void k_gemm1(const float* __restrict__ X,
                                               const float* __restrict__ W, int n) {
    __shared__ float Ws[32 * 128];   // [k][c]
    __shared__ float Xs[64 * 32];    // [r][k]
    int tid  = threadIdx.x;
    int r0   = (tid >> 4) * 4;
    int c0   = (tid & 15) * 8;
    int row0 = blockIdx.x * 64;

    unsigned long long acc[4][4];
#pragma unroll
    for (int i = 0; i < 4; i++)
#pragma unroll
        for (int j = 0; j < 4; j++) acc[i][j] = 0ull;

    for (int kc = 0; kc < CH; kc += 32) {
        __syncthreads();
#pragma unroll
        for (int j = 0; j < 4; j++) {
            int idx4 = tid + j * 256;
            int k = idx4 >> 5, c = (idx4 & 31) * 4;
            *(float4*)&Ws[k * 128 + c] = *(const float4*)&W[(size_t)(kc + k) * 128 + c];
        }
#pragma unroll
        for (int j = 0; j < 2; j++) {
            int idx4 = tid + j * 256;
            int r = idx4 >> 3, k = (idx4 & 7) * 4;
            float4 v = make_float4(0.f, 0.f, 0.f, 0.f);
            if (row0 + r < n) v = *(const float4*)&X[(size_t)(row0 + r) * 128 + kc + k];
            *(float4*)&Xs[r * 32 + k] = v;
        }
        __syncthreads();

#pragma unroll 8
        for (int k = 0; k < 32; k++) {
            ulonglong2 wa = *(const ulonglong2*)&Ws[k * 128 + c0];
            ulonglong2 wb = *(const ulonglong2*)&Ws[k * 128 + c0 + 4];
#pragma unroll
            for (int i = 0; i < 4; i++) {
                float xf = Xs[(r0 + i) * 32 + k];
                unsigned long long xp; PACK_DUP(xp, xf);
                FMA_F32X2(acc[i][0], xp, wa.x);
                FMA_F32X2(acc[i][1], xp, wa.y);
                FMA_F32X2(acc[i][2], xp, wb.x);
                FMA_F32X2(acc[i][3], xp, wb.y);
            }
        }
    }
#pragma unroll
    for (int i = 0; i < 4; i++) {
        int row = row0 + r0 + i;
        if (row < n) {
            float4 v0, v1;
            UNPACK2(v0.x, v0.y, acc[i][0]); UNPACK2(v0.z, v0.w, acc[i][1]);
            UNPACK2(v1.x, v1.y, acc[i][2]); UNPACK2(v1.z, v1.w, acc[i][3]);
            *(float4*)&g_H[(size_t)row * 128 + c0]     = v0;
            *(float4*)&g_H[(size_t)row * 128 + c0 + 4] = v1;
        }
    }
}

// ---------------- device helper: warp-gather one node row into a float4 ----------------
__device__ __forceinline__ float4 gather_row(const float* __restrict__ H,
                                             int node, int lane) {
    int beg = g_ptr[node], end = g_ptr[node + 1];
    float dn = g_dinv[node];
    float s0 = dn * dn;
    float4 acc = ((const float4*)(H + (size_t)node * CH))[lane];   // self loop
    acc.x *= s0; acc.y *= s0; acc.z *= s0; acc.w *= s0;

    int j = beg;
    for (; j + 4 <= end; j += 4) {
        int2 p0 = g_edge[j], p1 = g_edge[j + 1], p2 = g_edge[j + 2], p3 = g_edge[j + 3];
        float4 v0 = ((const float4*)(H + (size_t)p0.x * CH))[lane];
        float4 v1 = ((const float4*)(H + (size_t)p1.x * CH))[lane];
        float4 v2 = ((const float4*)(H + (size_t)p2.x * CH))[lane];
        float4 v3 = ((const float4*)(H + (size_t)p3.x * CH))[lane];
        float w0 = __int_as_float(p0.y), w1 = __int_as_float(p1.y);
        float w2 = __int_as_float(p2.y), w3 = __int_as_float(p3.y);
        acc.x += v0.x * w0 + v1.x * w1 + v2.x * w2 + v3.x * w3;
        acc.y += v0.y * w0 + v1.y * w1 + v2.y * w2 + v3.y * w3;
        acc.z += v0.z * w0 + v1.z * w1 + v2.z * w2 + v3.z * w3;
        acc.w += v0.w * w0 + v1.w * w1 + v2.w * w2 + v3.w * w3;
    }
    for (; j < end; j++) {
        int2 p = g_edge[j];
        float w = __int_as_float(p.y);
        float4 v = ((const float4*)(H + (size_t)p.x * CH))[lane];
        acc.x += v.x * w; acc.y += v.y * w;
        acc.z += v.z * w; acc.w += v.w * w;
    }
    return acc;
}

// ---------------- gather pass 1: hidden = relu(A_hat @ H + b1) ----------------
__global__ __launch_bounds__(256) void k_gather0(const float* __restrict__ b1, int n) {
    int gt = blockIdx.x * blockDim.x + threadIdx.x;
    int node = gt >> 5, lane = gt & 31;
    if (node >= n) return;
    float4 acc = gather_row(g_H, node, lane);
    float4 bv = *(const float4*)&b1[lane * 4];
    acc.x = fmaxf(acc.x + bv.x, 0.f); acc.y = fmaxf(acc.y + bv.y, 0.f);
    acc.z = fmaxf(acc.z + bv.z, 0.f); acc.w = fmaxf(acc.w + bv.w, 0.f);
    ((float4*)(g_hidden + (size_t)node * CH))[lane] = acc;
}

// ---------------- fused: Xs = A_hat @ hidden (64 rows, smem), then
//                  out = relu(Xs @ [W2|W3] + [b2|b3]) -> (x1, x2) ----------------
__global__ __launch_bounds__(256) void k_gather_gemm2(const float* __restrict__ W2,
                                                      const float* __restrict__ W3,
                                                      const float* __restrict__ b2,
                                                      const float* __restrict__ b3,
                                                      float* __restrict__ out, int n) {
    __shared__ float Xs[64 * 128];   // 32 KB: full K rows for this block
    __shared__ float Ws[32 * 128];   // 16 KB: one K-chunk of [W2|W3]
    int tid   = threadIdx.x;
    int w     = tid >> 5;
    int lane  = tid & 31;
    int node0 = blockIdx.x * 64;

    // Phase 1: warp w gathers nodes node0 + w*8 .. +7 into Xs
#pragma unroll 1
    for (int i = 0; i < 8; i++) {
        int nl = w * 8 + i;
        int node = node0 + nl;
        float4 acc = make_float4(0.f, 0.f, 0.f, 0.f);
        if (node < n) acc = gather_row(g_hidden, node, lane);
        *(float4*)&Xs[nl * 128 + lane * 4] = acc;
    }

    // Phase 2: GEMM from smem
    int r0 = (tid >> 4) * 4;
    int c0 = (tid & 15) * 8;

    unsigned long long acc[4][4];
#pragma unroll
    for (int i = 0; i < 4; i++)
#pragma unroll
        for (int j = 0; j < 4; j++) acc[i][j] = 0ull;

    for (int kc = 0; kc < CH; kc += 32) {
        __syncthreads();   // Xs done (first iter) / Ws consumed (later iters)
#pragma unroll
        for (int j = 0; j < 4; j++) {
            int idx4 = tid + j * 256;
            int k = idx4 >> 5, c = (idx4 & 31) * 4;
            float4 v;
            if (c < OUTC) v = *(const float4*)&W2[(size_t)(kc + k) * OUTC + c];
            else          v = *(const float4*)&W3[(size_t)(kc + k) * OUTC + (c - OUTC)];
            *(float4*)&Ws[k * 128 + c] = v;
        }
        __syncthreads();

#pragma unroll 8
        for (int k = 0; k < 32; k++) {
            ulonglong2 wa = *(const ulonglong2*)&Ws[k * 128 + c0];
            ulonglong2 wb = *(const ulonglong2*)&Ws[k * 128 + c0 + 4];
#pragma unroll
            for (int i = 0; i < 4; i++) {
                float xf = Xs[(r0 + i) * 128 + kc + k];
                unsigned long long xp; PACK_DUP(xp, xf);
                FMA_F32X2(acc[i][0], xp, wa.x);
                FMA_F32X2(acc[i][1], xp, wa.y);
                FMA_F32X2(acc[i][2], xp, wb.x);
                FMA_F32X2(acc[i][3], xp, wb.y);
            }
        }
    }

    // epilogue: bias (from global, L1-hot) + relu + split store
    const float* bsrc = (c0 < OUTC) ? &b2[c0] : &b3[c0 - OUTC];
    float4 bv0 = *(const float4*)&bsrc[0];
    float4 bv1 = *(const float4*)&bsrc[4];
    size_t half = (size_t)n * OUTC;
#pragma unroll
    for (int i = 0; i < 4; i++) {
        int row = node0 + r0 + i;
        if (row < n) {
            float4 v0, v1;
            UNPACK2(v0.x, v0.y, acc[i][0]); UNPACK2(v0.z, v0.w, acc[i][1]);
            UNPACK2(v1.x, v1.y, acc[i][2]); UNPACK2(v1.z, v1.w, acc[i][3]);
            v0.x = fmaxf(v0.x + bv0.x, 0.f); v0.y = fmaxf(v0.y + bv0.y, 0.f);
            v0.z = fmaxf(v0.z + bv0.z, 0.f); v0.w = fmaxf(v0.w + bv0.w, 0.f);
            v1.x = fmaxf(v1.x + bv1.x, 0.f); v1.y = fmaxf(v1.y + bv1.y, 0.f);
            v1.z = fmaxf(v1.z + bv1.z, 0.f); v1.w = fmaxf(v1.w + bv1.w, 0.f);
            float* base = (c0 < OUTC) ? &out[(size_t)row * OUTC + c0]
                                      : &out[half + (size_t)row * OUTC + (c0 - OUTC)];
            *(float4*)base       = v0;
            *(float4*)(base + 4) = v1;
        }
    }
}

extern "C" void kernel_launch(void* const* d_in, const int* in_sizes, int n_in,
                              void* d_out, int out_size) {
    const float* x  = (const float*)d_in[0];
    const void*  ei = d_in[1];
    const float* W1 = (const float*)d_in[2];
    const float* b1 = (const float*)d_in[3];
    const float* W2 = (const float*)d_in[4];
    const float* b2 = (const float*)d_in[5];
    const float* W3 = (const float*)d_in[6];
    const float* b3 = (const float*)d_in[7];
    float* out = (float*)d_out;

    int nN = in_sizes[0] / CH;   // 50000
    int nE = in_sizes[1] / 2;    // 800000
    int tb = 256;
    int nb = (nN + 1023) / 1024;

    // CSR build (6 launches)
    k_zero <<<(nN + tb - 1) / tb, tb>>>(nN);
    k_count<<<(nE + tb - 1) / tb, tb>>>(ei, nE);
    k_scan1<<<nb, 1024>>>(nN);
    k_scan2<<<1, 32>>>(nb);
    k_scan3<<<(nN + tb - 1) / tb, tb>>>(nN);
    k_fill <<<(nE + tb - 1) / tb, tb>>>(ei, nE);

    // layer 1: H = x @ W1
    k_gemm1<<<(nN + 63) / 64, 256>>>(x, W1, nN);
    // hidden = relu(A_hat @ H + b1)
    k_gather0<<<(nN * 32 + tb - 1) / tb, tb>>>(b1, nN);
    // out = relu((A_hat @ hidden) @ [W2|W3] + bias) -> (x1, x2)
    k_gather_gemm2<<<(nN + 63) / 64, 256>>>(W2, W3, b2, b3, out, nN);
}

// round 10
// speedup vs baseline: 1.4999x; 1.1203x over previous
#include <cuda_runtime.h>
#include <cuda_fp16.h>

#define MAX_NODES 50000
#define MAX_EDGES 800000
#define CH 128
#define OUTC 64

// ---- device scratch ----
__device__ __half g_H[MAX_NODES * CH];       // x @ W1          (fp16 storage)
__device__ __half g_hidden[MAX_NODES * CH];  // relu(A_hat@H+b1) (fp16 storage)
__device__ int    g_deg[MAX_NODES];
__device__ float  g_dinv[MAX_NODES];
// CSR by target node; edge payload packed as {src:int, nrm:float}
__device__ int    g_ptr[MAX_NODES + 1];
__device__ int    g_cursor[MAX_NODES];
__device__ int2   g_edge[MAX_EDGES];
__device__ int    g_bsum[64];

#define FMA_F32X2(acc, a, b) \
    asm("fma.rn.f32x2 %0, %1, %2, %0;" : "+l"(acc) : "l"(a), "l"(b))
#define PACK_DUP(d, f) \
    asm("mov.b64 %0, {%1, %1};" : "=l"(d) : "f"(f))
#define UNPACK2(lo, hi, p) \
    asm("mov.b64 {%0, %1}, %2;" : "=f"(lo), "=f"(hi) : "l"(p))

// Per-block int64-vs-int32 edge dtype detection (odd words all zero => int64).
__device__ __forceinline__ int detect_is64(const void* ei) {
    __shared__ int s_is64;
    if (threadIdx.x < 32) {
        int w = ((const int*)ei)[2 * threadIdx.x + 1];
        unsigned m = __ballot_sync(~0u, w == 0);
        if (threadIdx.x == 0) s_is64 = (m == ~0u);
    }
    __syncthreads();
    return s_is64;
}

__device__ __forceinline__ int edge_at(const void* ei, int i, int is64) {
    if (is64) return (int)((const long long*)ei)[i];
    return ((const int*)ei)[i];
}

// ---------------- degree ----------------
__global__ void k_zero(int n) {
    int i = blockIdx.x * blockDim.x + threadIdx.x;
    if (i < n) g_deg[i] = 0;
}

__global__ void k_count(const void* __restrict__ ei, int nE) {
    int is64 = detect_is64(ei);
    int e = blockIdx.x * blockDim.x + threadIdx.x;
    if (e < nE) atomicAdd(&g_deg[edge_at(ei, nE + e, is64)], 1);
}

// ---------------- CSR build: scan (+dinv fused) + offsets + fill ----------------
__global__ __launch_bounds__(1024) void k_scan1(int n) {
    __shared__ int wsum[32];
    int i = blockIdx.x * 1024 + threadIdx.x;
    int lane = threadIdx.x & 31, wid = threadIdx.x >> 5;
    int d = (i < n) ? g_deg[i] : 0;
    if (i < n) g_dinv[i] = rsqrtf((float)(d + 1));   // +1 self loop
    int s = d;
#pragma unroll
    for (int o = 1; o < 32; o <<= 1) {
        int t = __shfl_up_sync(~0u, s, o);
        if (lane >= o) s += t;
    }
    if (lane == 31) wsum[wid] = s;
    __syncthreads();
    if (wid == 0) {
        int ws = wsum[lane];
#pragma unroll
        for (int o = 1; o < 32; o <<= 1) {
            int t = __shfl_up_sync(~0u, ws, o);
            if (lane >= o) ws += t;
        }
        wsum[lane] = ws;
    }
    __syncthreads();
    int incl = s + (wid > 0 ? wsum[wid - 1] : 0);
    if (i < n) g_ptr[i + 1] = incl;
    if (threadIdx.x == 1023) g_bsum[blockIdx.x] = incl;
}

// finalize ptr with block offsets (<=64 blocks of 1024) + init cursor
__global__ __launch_bounds__(256) void k_scan3(int n) {
    __shared__ int s_off;
    int b = blockIdx.x >> 2;   // which 1024-index scan1 block
    if (threadIdx.x < 32) {
        int s = 0;
        if (threadIdx.x < b)      s  = g_bsum[threadIdx.x];
        if (threadIdx.x + 32 < b) s += g_bsum[threadIdx.x + 32];
#pragma unroll
        for (int o = 16; o; o >>= 1) s += __shfl_down_sync(~0u, s, o);
        if (threadIdx.x == 0) s_off = s;
    }
    __syncthreads();
    int i = blockIdx.x * 256 + threadIdx.x;
    if (i < n) {
        int p1 = g_ptr[i + 1] + s_off;
        g_ptr[i + 1] = p1;
        g_cursor[i] = p1 - g_deg[i];
    }
    if (i == 0) g_ptr[0] = 0;
}

__global__ void k_fill(const void* __restrict__ ei, int nE) {
    int is64 = detect_is64(ei);
    int e = blockIdx.x * blockDim.x + threadIdx.x;
    if (e < nE) {
        int r = edge_at(ei, e, is64);
        int c = edge_at(ei, nE + e, is64);
        int pos = atomicAdd(&g_cursor[c], 1);
        g_edge[pos] = make_int2(r, __float_as_int(g_dinv[r] * g_dinv[c]));
    }
}

// ---------------- GEMM layer 1: g_H = fp16(x[n,128] @ W1[128,128]) ----------------
__global__ __launch_bounds__(256) void k_gemm1(const float* __restrict__ X,
                                               const float* __restrict__ W, int n) {
    __shared__ float Ws[32 * 128];   // [k][c]
    __shared__ float Xs[64 * 32];    // [r][k]
    int tid  = threadIdx.x;
    int r0   = (tid >> 4) * 4;
    int c0   = (tid & 15) * 8;
    int row0 = blockIdx.x * 64;

    unsigned long long acc[4][4];
#pragma unroll
    for (int i = 0; i < 4; i++)
#pragma unroll
        for (int j = 0; j < 4; j++) acc[i][j] = 0ull;

    for (int kc = 0; kc < CH; kc += 32) {
        __syncthreads();
#pragma unroll
        for (int j = 0; j < 4; j++) {
            int idx4 = tid + j * 256;
            int k = idx4 >> 5, c = (idx4 & 31) * 4;
            *(float4*)&Ws[k * 128 + c] = *(const float4*)&W[(size_t)(kc + k) * 128 + c];
        }
#pragma unroll
        for (int j = 0; j < 2; j++) {
            int idx4 = tid + j * 256;
            int r = idx4 >> 3, k = (idx4 & 7) * 4;
            float4 v = make_float4(0.f, 0.f, 0.f, 0.f);
            if (row0 + r < n) v = *(const float4*)&X[(size_t)(row0 + r) * 128 + kc + k];
            *(float4*)&Xs[r * 32 + k] = v;
        }
        __syncthreads();

#pragma unroll 8
        for (int k = 0; k < 32; k++) {
            ulonglong2 wa = *(const ulonglong2*)&Ws[k * 128 + c0];
            ulonglong2 wb = *(const ulonglong2*)&Ws[k * 128 + c0 + 4];
#pragma unroll
            for (int i = 0; i < 4; i++) {
                float xf = Xs[(r0 + i) * 32 + k];
                unsigned long long xp; PACK_DUP(xp, xf);
                FMA_F32X2(acc[i][0], xp, wa.x);
                FMA_F32X2(acc[i][1], xp, wa.y);
                FMA_F32X2(acc[i][2], xp, wb.x);
                FMA_F32X2(acc[i][3], xp, wb.y);
            }
        }
    }
#pragma unroll
    for (int i = 0; i < 4; i++) {
        int row = row0 + r0 + i;
        if (row < n) {
            float4 v0, v1;
            UNPACK2(v0.x, v0.y, acc[i][0]); UNPACK2(v0.z, v0.w, acc[i][1]);
            UNPACK2(v1.x, v1.y, acc[i][2]); UNPACK2(v1.z, v1.w, acc[i][3]);
            int4 pk;
            ((__half2*)&pk)[0] = __floats2half2_rn(v0.x, v0.y);
            ((__half2*)&pk)[1] = __floats2half2_rn(v0.z, v0.w);
            ((__half2*)&pk)[2] = __floats2half2_rn(v1.x, v1.y);
            ((__half2*)&pk)[3] = __floats2half2_rn(v1.z, v1.w);
            *(int4*)&g_H[(size_t)row * 128 + c0] = pk;
        }
    }
}

// ---------------- fp16-row gather helpers (16 lanes per node, 8 ch per lane) ----------------
__device__ __forceinline__ void cvt8(int4 raw, float o[8]) {
    const __half2* h = (const __half2*)&raw;
    float2 a = __half22float2(h[0]), b = __half22float2(h[1]);
    float2 c = __half22float2(h[2]), d = __half22float2(h[3]);
    o[0] = a.x; o[1] = a.y; o[2] = b.x; o[3] = b.y;
    o[4] = c.x; o[5] = c.y; o[6] = d.x; o[7] = d.y;
}

__device__ __forceinline__ void gather_row_h(const __half* __restrict__ Hh,
                                             int node, int l, float f[8]) {
    float dn = g_dinv[node];
    float s0 = dn * dn;
    int4 raw = *(const int4*)(Hh + (size_t)node * CH + l * 8);
    float t[8]; cvt8(raw, t);
#pragma unroll
    for (int k = 0; k < 8; k++) f[k] = t[k] * s0;   // self loop

    int beg = g_ptr[node], end = g_ptr[node + 1];
    int j = beg;
    for (; j + 4 <= end; j += 4) {
        int2 p0 = g_edge[j], p1 = g_edge[j + 1], p2 = g_edge[j + 2], p3 = g_edge[j + 3];
        int4 r0 = *(const int4*)(Hh + (size_t)p0.x * CH + l * 8);
        int4 r1 = *(const int4*)(Hh + (size_t)p1.x * CH + l * 8);
        int4 r2 = *(const int4*)(Hh + (size_t)p2.x * CH + l * 8);
        int4 r3 = *(const int4*)(Hh + (size_t)p3.x * CH + l * 8);
        float w0 = __int_as_float(p0.y), w1 = __int_as_float(p1.y);
        float w2 = __int_as_float(p2.y), w3 = __int_as_float(p3.y);
        float t0[8], t1[8], t2[8], t3[8];
        cvt8(r0, t0); cvt8(r1, t1); cvt8(r2, t2); cvt8(r3, t3);
#pragma unroll
        for (int k = 0; k < 8; k++)
            f[k] += t0[k] * w0 + t1[k] * w1 + t2[k] * w2 + t3[k] * w3;
    }
    for (; j < end; j++) {
        int2 p = g_edge[j];
        int4 r = *(const int4*)(Hh + (size_t)p.x * CH + l * 8);
        float w = __int_as_float(p.y);
        float t0[8]; cvt8(r, t0);
#pragma unroll
        for (int k = 0; k < 8; k++) f[k] += t0[k] * w;
    }
}

// ---------------- gather pass 1: hidden = fp16(relu(A_hat @ H + b1)) ----------------
__global__ __launch_bounds__(256) void k_gather0(const float* __restrict__ b1, int n) {
    int gt = blockIdx.x * 256 + threadIdx.x;
    int node = gt >> 4, l = gt & 15;
    if (node >= n) return;
    float f[8];
    gather_row_h(g_H, node, l, f);
    float4 ba = *(const float4*)&b1[l * 8];
    float4 bb = *(const float4*)&b1[l * 8 + 4];
    f[0] = fmaxf(f[0] + ba.x, 0.f); f[1] = fmaxf(f[1] + ba.y, 0.f);
    f[2] = fmaxf(f[2] + ba.z, 0.f); f[3] = fmaxf(f[3] + ba.w, 0.f);
    f[4] = fmaxf(f[4] + bb.x, 0.f); f[5] = fmaxf(f[5] + bb.y, 0.f);
    f[6] = fmaxf(f[6] + bb.z, 0.f); f[7] = fmaxf(f[7] + bb.w, 0.f);
    int4 pk;
    ((__half2*)&pk)[0] = __floats2half2_rn(f[0], f[1]);
    ((__half2*)&pk)[1] = __floats2half2_rn(f[2], f[3]);
    ((__half2*)&pk)[2] = __floats2half2_rn(f[4], f[5]);
    ((__half2*)&pk)[3] = __floats2half2_rn(f[6], f[7]);
    *(int4*)&g_hidden[(size_t)node * CH + l * 8] = pk;
}

// ---------------- fused: Xs = A_hat @ hidden (64 rows), then
//                  out = relu(Xs @ [W2|W3] + [b2|b3]) -> (x1, x2) ----------------
__global__ __launch_bounds__(256) void k_gather_gemm2(const float* __restrict__ W2,
                                                      const float* __restrict__ W3,
                                                      const float* __restrict__ b2,
                                                      const float* __restrict__ b3,
                                                      float* __restrict__ out, int n) {
    __shared__ float Xs[64 * 128];   // 32 KB
    __shared__ float Ws[32 * 128];   // 16 KB
    int tid   = threadIdx.x;
    int g     = tid >> 4;     // 16 groups of 16 lanes
    int l     = tid & 15;
    int node0 = blockIdx.x * 64;

    // Phase 1: group g gathers nodes node0 + g*4 .. +3
#pragma unroll 1
    for (int i = 0; i < 4; i++) {
        int nl = g * 4 + i;
        int node = node0 + nl;
        float f[8] = {0.f, 0.f, 0.f, 0.f, 0.f, 0.f, 0.f, 0.f};
        if (node < n) gather_row_h(g_hidden, node, l, f);
        *(float4*)&Xs[nl * 128 + l * 8]     = make_float4(f[0], f[1], f[2], f[3]);
        *(float4*)&Xs[nl * 128 + l * 8 + 4] = make_float4(f[4], f[5], f[6], f[7]);
    }

    // Phase 2: GEMM from smem
    int r0 = (tid >> 4) * 4;
    int c0 = (tid & 15) * 8;

    unsigned long long acc[4][4];
#pragma unroll
    for (int i = 0; i < 4; i++)
#pragma unroll
        for (int j = 0; j < 4; j++) acc[i][j] = 0ull;

    for (int kc = 0; kc < CH; kc += 32) {
        __syncthreads();
#pragma unroll
        for (int j = 0; j < 4; j++) {
            int idx4 = tid + j * 256;
            int k = idx4 >> 5, c = (idx4 & 31) * 4;
            float4 v;
            if (c < OUTC) v = *(const float4*)&W2[(size_t)(kc + k) * OUTC + c];
            else          v = *(const float4*)&W3[(size_t)(kc + k) * OUTC + (c - OUTC)];
            *(float4*)&Ws[k * 128 + c] = v;
        }
        __syncthreads();

#pragma unroll 8
        for (int k = 0; k < 32; k++) {
            ulonglong2 wa = *(const ulonglong2*)&Ws[k * 128 + c0];
            ulonglong2 wb = *(const ulonglong2*)&Ws[k * 128 + c0 + 4];
#pragma unroll
            for (int i = 0; i < 4; i++) {
                float xf = Xs[(r0 + i) * 128 + kc + k];
                unsigned long long xp; PACK_DUP(xp, xf);
                FMA_F32X2(acc[i][0], xp, wa.x);
                FMA_F32X2(acc[i][1], xp, wa.y);
                FMA_F32X2(acc[i][2], xp, wb.x);
                FMA_F32X2(acc[i][3], xp, wb.y);
            }
        }
    }

    const float* bsrc = (c0 < OUTC) ? &b2[c0] : &b3[c0 - OUTC];
    float4 bv0 = *(const float4*)&bsrc[0];
    float4 bv1 = *(const float4*)&bsrc[4];
    size_t half_off = (size_t)n * OUTC;
#pragma unroll
    for (int i = 0; i < 4; i++) {
        int row = node0 + r0 + i;
        if (row < n) {
            float4 v0, v1;
            UNPACK2(v0.x, v0.y, acc[i][0]); UNPACK2(v0.z, v0.w, acc[i][1]);
            UNPACK2(v1.x, v1.y, acc[i][2]); UNPACK2(v1.z, v1.w, acc[i][3]);
            v0.x = fmaxf(v0.x + bv0.x, 0.f); v0.y = fmaxf(v0.y + bv0.y, 0.f);
            v0.z = fmaxf(v0.z + bv0.z, 0.f); v0.w = fmaxf(v0.w + bv0.w, 0.f);
            v1.x = fmaxf(v1.x + bv1.x, 0.f); v1.y = fmaxf(v1.y + bv1.y, 0.f);
            v1.z = fmaxf(v1.z + bv1.z, 0.f); v1.w = fmaxf(v1.w + bv1.w, 0.f);
            float* base = (c0 < OUTC) ? &out[(size_t)row * OUTC + c0]
                                      : &out[half_off + (size_t)row * OUTC + (c0 - OUTC)];
            *(float4*)base       = v0;
            *(float4*)(base + 4) = v1;
        }
    }
}

extern "C" void kernel_launch(void* const* d_in, const int* in_sizes, int n_in,
                              void* d_out, int out_size) {
    const float* x  = (const float*)d_in[0];
    const void*  ei = d_in[1];
    const float* W1 = (const float*)d_in[2];
    const float* b1 = (const float*)d_in[3];
    const float* W2 = (const float*)d_in[4];
    const float* b2 = (const float*)d_in[5];
    const float* W3 = (const float*)d_in[6];
    const float* b3 = (const float*)d_in[7];
    float* out = (float*)d_out;

    int nN = in_sizes[0] / CH;   // 50000
    int nE = in_sizes[1] / 2;    // 800000
    int tb = 256;
    int nb = (nN + 1023) / 1024;

    // CSR build (5 launches)
    k_zero <<<(nN + tb - 1) / tb, tb>>>(nN);
    k_count<<<(nE + tb - 1) / tb, tb>>>(ei, nE);
    k_scan1<<<nb, 1024>>>(nN);
    k_scan3<<<(nN + tb - 1) / tb, tb>>>(nN);
    k_fill <<<(nE + tb - 1) / tb, tb>>>(ei, nE);

    // layer 1: H = fp16(x @ W1)
    k_gemm1<<<(nN + 63) / 64, 256>>>(x, W1, nN);
    // hidden = fp16(relu(A_hat @ H + b1))
    k_gather0<<<(nN * 16 + tb - 1) / tb, tb>>>(b1, nN);
    // out = relu((A_hat @ hidden) @ [W2|W3] + bias) -> (x1, x2)
    k_gather_gemm2<<<(nN + 63) / 64, 256>>>(W2, W3, b2, b3, out, nN);
}

// round 11
// speedup vs baseline: 2.8438x; 1.8959x over previous
#include <cuda_runtime.h>
#include <cuda_fp16.h>

#define MAX_NODES 50000
#define MAX_EDGES 800000
#define CH 128
#define OUTC 64

// ---- device scratch ----
__device__ __half g_H[MAX_NODES * CH];       // fp16(x @ W1)
__device__ __half g_hidden[MAX_NODES * CH];  // fp16(relu(A_hat@H+b1))
__device__ int    g_deg[MAX_NODES];
__device__ float  g_dinv[MAX_NODES];
// CSR by target node; edge payload {src:int, nrm:float}
__device__ int    g_ptr[MAX_NODES + 1];
__device__ int    g_cursor[MAX_NODES];
__device__ int2   g_edge[MAX_EDGES];
__device__ int    g_bsum[64];

// ---------------- mma / ldmatrix macros ----------------
#define LDSM_X4(r0, r1, r2, r3, addr) \
    asm volatile("ldmatrix.sync.aligned.m8n8.x4.shared.b16 {%0,%1,%2,%3}, [%4];" \
                 : "=r"(r0), "=r"(r1), "=r"(r2), "=r"(r3) : "r"(addr))
#define LDSM_X4_T(r0, r1, r2, r3, addr) \
    asm volatile("ldmatrix.sync.aligned.m8n8.x4.trans.shared.b16 {%0,%1,%2,%3}, [%4];" \
                 : "=r"(r0), "=r"(r1), "=r"(r2), "=r"(r3) : "r"(addr))
#define MMA16816(c0, c1, c2, c3, a0, a1, a2, a3, b0, b1) \
    asm volatile("mma.sync.aligned.m16n8k16.row.col.f32.f16.f16.f32 " \
                 "{%0,%1,%2,%3}, {%4,%5,%6,%7}, {%8,%9}, {%0,%1,%2,%3};" \
                 : "+f"(c0), "+f"(c1), "+f"(c2), "+f"(c3) \
                 : "r"(a0), "r"(a1), "r"(a2), "r"(a3), "r"(b0), "r"(b1))

// XOR swizzle for 256B rows (128 halves): spreads the 16 16B-chunks so that
// 8 consecutive rows at the same chunk hit 8 distinct banks (ldmatrix-safe).
__device__ __forceinline__ int swz(int row, int colh) {
    int chunk = colh >> 3;
    chunk = (chunk & 8) | ((chunk ^ row) & 7);
    return row * 128 + chunk * 8 + (colh & 7);
}

// Per-block int64-vs-int32 edge dtype detection (odd words all zero => int64).
__device__ __forceinline__ int detect_is64(const void* ei) {
    __shared__ int s_is64;
    if (threadIdx.x < 32) {
        int w = ((const int*)ei)[2 * threadIdx.x + 1];
        unsigned m = __ballot_sync(~0u, w == 0);
        if (threadIdx.x == 0) s_is64 = (m == ~0u);
    }
    __syncthreads();
    return s_is64;
}

__device__ __forceinline__ int edge_at(const void* ei, int i, int is64) {
    if (is64) return (int)((const long long*)ei)[i];
    return ((const int*)ei)[i];
}

// ---------------- degree ----------------
__global__ void k_zero(int n) {
    int i = blockIdx.x * blockDim.x + threadIdx.x;
    if (i < n) g_deg[i] = 0;
}

__global__ void k_count(const void* __restrict__ ei, int nE) {
    int is64 = detect_is64(ei);
    int e = blockIdx.x * blockDim.x + threadIdx.x;
    if (e < nE) atomicAdd(&g_deg[edge_at(ei, nE + e, is64)], 1);
}

// ---------------- CSR build ----------------
__global__ __launch_bounds__(1024) void k_scan1(int n) {
    __shared__ int wsum[32];
    int i = blockIdx.x * 1024 + threadIdx.x;
    int lane = threadIdx.x & 31, wid = threadIdx.x >> 5;
    int d = (i < n) ? g_deg[i] : 0;
    if (i < n) g_dinv[i] = rsqrtf((float)(d + 1));   // +1 self loop
    int s = d;
#pragma unroll
    for (int o = 1; o < 32; o <<= 1) {
        int t = __shfl_up_sync(~0u, s, o);
        if (lane >= o) s += t;
    }
    if (lane == 31) wsum[wid] = s;
    __syncthreads();
    if (wid == 0) {
        int ws = wsum[lane];
#pragma unroll
        for (int o = 1; o < 32; o <<= 1) {
            int t = __shfl_up_sync(~0u, ws, o);
            if (lane >= o) ws += t;
        }
        wsum[lane] = ws;
    }
    __syncthreads();
    int incl = s + (wid > 0 ? wsum[wid - 1] : 0);
    if (i < n) g_ptr[i + 1] = incl;
    if (threadIdx.x == 1023) g_bsum[blockIdx.x] = incl;
}

__global__ __launch_bounds__(256) void k_scan3(int n) {
    __shared__ int s_off;
    int b = blockIdx.x >> 2;
    if (threadIdx.x < 32) {
        int s = 0;
        if (threadIdx.x < b)      s  = g_bsum[threadIdx.x];
        if (threadIdx.x + 32 < b) s += g_bsum[threadIdx.x + 32];
#pragma unroll
        for (int o = 16; o; o >>= 1) s += __shfl_down_sync(~0u, s, o);
        if (threadIdx.x == 0) s_off = s;
    }
    __syncthreads();
    int i = blockIdx.x * 256 + threadIdx.x;
    if (i < n) {
        int p1 = g_ptr[i + 1] + s_off;
        g_ptr[i + 1] = p1;
        g_cursor[i] = p1 - g_deg[i];
    }
    if (i == 0) g_ptr[0] = 0;
}

__global__ void k_fill(const void* __restrict__ ei, int nE) {
    int is64 = detect_is64(ei);
    int e = blockIdx.x * blockDim.x + threadIdx.x;
    if (e < nE) {
        int r = edge_at(ei, e, is64);
        int c = edge_at(ei, nE + e, is64);
        int pos = atomicAdd(&g_cursor[c], 1);
        g_edge[pos] = make_int2(r, __float_as_int(g_dinv[r] * g_dinv[c]));
    }
}

// ---------------- fp32x8 -> swizzled fp16 smem store ----------------
__device__ __forceinline__ void st_chunk_h(__half* S, int row, int chunk,
                                           float4 u, float4 v) {
    int4 pk;
    ((__half2*)&pk)[0] = __floats2half2_rn(u.x, u.y);
    ((__half2*)&pk)[1] = __floats2half2_rn(u.z, u.w);
    ((__half2*)&pk)[2] = __floats2half2_rn(v.x, v.y);
    ((__half2*)&pk)[3] = __floats2half2_rn(v.z, v.w);
    *(int4*)&S[swz(row, chunk * 8)] = pk;
}

// ---------------- mma mainloop: C[8][4] += As(64x128) @ Wh(128x128) ----------------
// 8 warps: wr = wid>>1 (16-row group), wc = wid&1 (64-col group).
__device__ __forceinline__ void mma_tile(const __half* As, const __half* Wh,
                                         float C[8][4], int wr, int wc, int lane) {
    unsigned a_base = (unsigned)__cvta_generic_to_shared(As);
    unsigned w_base = (unsigned)__cvta_generic_to_shared(Wh);
#pragma unroll
    for (int ks = 0; ks < 8; ks++) {
        unsigned r0, r1, r2, r3;
        int arow = wr * 16 + (lane & 15);
        int acolh = ks * 16 + ((lane >> 4) << 3);
        unsigned a0, a1, a2, a3;
        LDSM_X4(a0, a1, a2, a3, a_base + swz(arow, acolh) * 2);
#pragma unroll
        for (int f2 = 0; f2 < 4; f2++) {
            int brow = ks * 16 + (lane & 15);
            int bcolh = wc * 64 + f2 * 16 + (((lane >> 4) & 1) << 3);
            LDSM_X4_T(r0, r1, r2, r3, w_base + swz(brow, bcolh) * 2);
            MMA16816(C[f2 * 2][0], C[f2 * 2][1], C[f2 * 2][2], C[f2 * 2][3],
                     a0, a1, a2, a3, r0, r1);
            MMA16816(C[f2 * 2 + 1][0], C[f2 * 2 + 1][1], C[f2 * 2 + 1][2], C[f2 * 2 + 1][3],
                     a0, a1, a2, a3, r2, r3);
        }
    }
}

// ---------------- GEMM layer 1: g_H = fp16(x @ W1)  (HMMA) ----------------
__global__ __launch_bounds__(256) void k_gemm1(const float* __restrict__ X,
                                               const float* __restrict__ W, int n) {
    __shared__ __half As[64 * 128];   // 16 KB
    __shared__ __half Wh[128 * 128];  // 32 KB
    int tid = threadIdx.x;
    int row0 = blockIdx.x * 64;

    // load W1 fp32 -> fp16 swizzled: 2048 chunk-tasks
#pragma unroll
    for (int j = 0; j < 8; j++) {
        int task = tid + j * 256;
        int k = task >> 4, ch = task & 15;
        float4 u = *(const float4*)&W[(size_t)k * 128 + ch * 8];
        float4 v = *(const float4*)&W[(size_t)k * 128 + ch * 8 + 4];
        st_chunk_h(Wh, k, ch, u, v);
    }
    // load X tile fp32 -> fp16 swizzled: 1024 chunk-tasks
#pragma unroll
    for (int j = 0; j < 4; j++) {
        int task = tid + j * 256;
        int r = task >> 4, ch = task & 15;
        float4 u = make_float4(0.f, 0.f, 0.f, 0.f), v = u;
        if (row0 + r < n) {
            u = *(const float4*)&X[(size_t)(row0 + r) * 128 + ch * 8];
            v = *(const float4*)&X[(size_t)(row0 + r) * 128 + ch * 8 + 4];
        }
        st_chunk_h(As, r, ch, u, v);
    }
    __syncthreads();

    int lane = tid & 31, wid = tid >> 5;
    int wr = wid >> 1, wc = wid & 1;
    float C[8][4];
#pragma unroll
    for (int f = 0; f < 8; f++)
#pragma unroll
        for (int q = 0; q < 4; q++) C[f][q] = 0.f;

    mma_tile(As, Wh, C, wr, wc, lane);

    // epilogue: fragments -> g_H fp16
    int g = lane >> 2, t = lane & 3;
#pragma unroll
    for (int f = 0; f < 8; f++) {
        int col = wc * 64 + f * 8 + t * 2;
        int row = row0 + wr * 16 + g;
        if (row < n)
            *(__half2*)&g_H[(size_t)row * 128 + col] = __floats2half2_rn(C[f][0], C[f][1]);
        if (row + 8 < n)
            *(__half2*)&g_H[(size_t)(row + 8) * 128 + col] = __floats2half2_rn(C[f][2], C[f][3]);
    }
}

// ---------------- fp16-row gather (16 lanes per node, 8 ch per lane) ----------------
__device__ __forceinline__ void cvt8(int4 raw, float o[8]) {
    const __half2* h = (const __half2*)&raw;
    float2 a = __half22float2(h[0]), b = __half22float2(h[1]);
    float2 c = __half22float2(h[2]), d = __half22float2(h[3]);
    o[0] = a.x; o[1] = a.y; o[2] = b.x; o[3] = b.y;
    o[4] = c.x; o[5] = c.y; o[6] = d.x; o[7] = d.y;
}

__device__ __forceinline__ void gather_row_h(const __half* __restrict__ Hh,
                                             int node, int l, float f[8]) {
    float dn = g_dinv[node];
    float s0 = dn * dn;
    int4 raw = *(const int4*)(Hh + (size_t)node * CH + l * 8);
    float t[8]; cvt8(raw, t);
#pragma unroll
    for (int k = 0; k < 8; k++) f[k] = t[k] * s0;   // self loop

    int beg = g_ptr[node], end = g_ptr[node + 1];
    int j = beg;
    for (; j + 4 <= end; j += 4) {
        int2 p0 = g_edge[j], p1 = g_edge[j + 1], p2 = g_edge[j + 2], p3 = g_edge[j + 3];
        int4 r0 = *(const int4*)(Hh + (size_t)p0.x * CH + l * 8);
        int4 r1 = *(const int4*)(Hh + (size_t)p1.x * CH + l * 8);
        int4 r2 = *(const int4*)(Hh + (size_t)p2.x * CH + l * 8);
        int4 r3 = *(const int4*)(Hh + (size_t)p3.x * CH + l * 8);
        float w0 = __int_as_float(p0.y), w1 = __int_as_float(p1.y);
        float w2 = __int_as_float(p2.y), w3 = __int_as_float(p3.y);
        float t0[8], t1[8], t2[8], t3[8];
        cvt8(r0, t0); cvt8(r1, t1); cvt8(r2, t2); cvt8(r3, t3);
#pragma unroll
        for (int k = 0; k < 8; k++)
            f[k] += t0[k] * w0 + t1[k] * w1 + t2[k] * w2 + t3[k] * w3;
    }
    for (; j < end; j++) {
        int2 p = g_edge[j];
        int4 r = *(const int4*)(Hh + (size_t)p.x * CH + l * 8);
        float w = __int_as_float(p.y);
        float t0[8]; cvt8(r, t0);
#pragma unroll
        for (int k = 0; k < 8; k++) f[k] += t0[k] * w;
    }
}

// ---------------- gather pass 1: hidden = fp16(relu(A_hat @ H + b1)) ----------------
__global__ __launch_bounds__(256) void k_gather0(const float* __restrict__ b1, int n) {
    int gt = blockIdx.x * 256 + threadIdx.x;
    int node = gt >> 4, l = gt & 15;
    if (node >= n) return;
    float f[8];
    gather_row_h(g_H, node, l, f);
    float4 ba = *(const float4*)&b1[l * 8];
    float4 bb = *(const float4*)&b1[l * 8 + 4];
    f[0] = fmaxf(f[0] + ba.x, 0.f); f[1] = fmaxf(f[1] + ba.y, 0.f);
    f[2] = fmaxf(f[2] + ba.z, 0.f); f[3] = fmaxf(f[3] + ba.w, 0.f);
    f[4] = fmaxf(f[4] + bb.x, 0.f); f[5] = fmaxf(f[5] + bb.y, 0.f);
    f[6] = fmaxf(f[6] + bb.z, 0.f); f[7] = fmaxf(f[7] + bb.w, 0.f);
    int4 pk;
    ((__half2*)&pk)[0] = __floats2half2_rn(f[0], f[1]);
    ((__half2*)&pk)[1] = __floats2half2_rn(f[2], f[3]);
    ((__half2*)&pk)[2] = __floats2half2_rn(f[4], f[5]);
    ((__half2*)&pk)[3] = __floats2half2_rn(f[6], f[7]);
    *(int4*)&g_hidden[(size_t)node * CH + l * 8] = pk;
}

// ---------------- fused: As = fp16(A_hat @ hidden) (64 rows), then HMMA GEMM,
//                  out = relu(As @ [W2|W3] + [b2|b3]) -> (x1, x2) ----------------
__global__ __launch_bounds__(256) void k_gather_gemm2(const float* __restrict__ W2,
                                                      const float* __restrict__ W3,
                                                      const float* __restrict__ b2,
                                                      const float* __restrict__ b3,
                                                      float* __restrict__ out, int n) {
    __shared__ __half As[64 * 128];   // 16 KB
    __shared__ __half Wh[128 * 128];  // 32 KB: [W2 | W3]
    int tid = threadIdx.x;
    int node0 = blockIdx.x * 64;

    // load fused weight fp32 -> fp16 swizzled
#pragma unroll
    for (int j = 0; j < 8; j++) {
        int task = tid + j * 256;
        int k = task >> 4, ch = task & 15;
        const float* src = (ch < 8) ? &W2[(size_t)k * OUTC + ch * 8]
                                    : &W3[(size_t)k * OUTC + (ch - 8) * 8];
        float4 u = *(const float4*)&src[0];
        float4 v = *(const float4*)&src[4];
        st_chunk_h(Wh, k, ch, u, v);
    }

    // gather phase: group g (16 lanes) gathers nodes node0 + g*4 .. +3 into As
    int gg = tid >> 4, l = tid & 15;
#pragma unroll 1
    for (int i = 0; i < 4; i++) {
        int nl = gg * 4 + i;
        int node = node0 + nl;
        float f[8] = {0.f, 0.f, 0.f, 0.f, 0.f, 0.f, 0.f, 0.f};
        if (node < n) gather_row_h(g_hidden, node, l, f);
        st_chunk_h(As, nl, l,
                   make_float4(f[0], f[1], f[2], f[3]),
                   make_float4(f[4], f[5], f[6], f[7]));
    }
    __syncthreads();

    int lane = tid & 31, wid = tid >> 5;
    int wr = wid >> 1, wc = wid & 1;
    float C[8][4];
#pragma unroll
    for (int f = 0; f < 8; f++)
#pragma unroll
        for (int q = 0; q < 4; q++) C[f][q] = 0.f;

    mma_tile(As, Wh, C, wr, wc, lane);

    // epilogue: bias + relu + split store (wc=0 -> x1, wc=1 -> x2)
    const float* bb = wc ? b3 : b2;
    float* ob = wc ? out + (size_t)n * OUTC : out;
    int g = lane >> 2, t = lane & 3;
#pragma unroll
    for (int f = 0; f < 8; f++) {
        int col = f * 8 + t * 2;
        float bx = bb[col], by = bb[col + 1];
        int row = node0 + wr * 16 + g;
        if (row < n) {
            float2 v = make_float2(fmaxf(C[f][0] + bx, 0.f), fmaxf(C[f][1] + by, 0.f));
            *(float2*)&ob[(size_t)row * OUTC + col] = v;
        }
        if (row + 8 < n) {
            float2 v = make_float2(fmaxf(C[f][2] + bx, 0.f), fmaxf(C[f][3] + by, 0.f));
            *(float2*)&ob[(size_t)(row + 8) * OUTC + col] = v;
        }
    }
}

extern "C" void kernel_launch(void* const* d_in, const int* in_sizes, int n_in,
                              void* d_out, int out_size) {
    const float* x  = (const float*)d_in[0];
    const void*  ei = d_in[1];
    const float* W1 = (const float*)d_in[2];
    const float* b1 = (const float*)d_in[3];
    const float* W2 = (const float*)d_in[4];
    const float* b2 = (const float*)d_in[5];
    const float* W3 = (const float*)d_in[6];
    const float* b3 = (const float*)d_in[7];
    float* out = (float*)d_out;

    int nN = in_sizes[0] / CH;   // 50000
    int nE = in_sizes[1] / 2;    // 800000
    int tb = 256;
    int nb = (nN + 1023) / 1024;

    // CSR build
    k_zero <<<(nN + tb - 1) / tb, tb>>>(nN);
    k_count<<<(nE + tb - 1) / tb, tb>>>(ei, nE);
    k_scan1<<<nb, 1024>>>(nN);
    k_scan3<<<(nN + tb - 1) / tb, tb>>>(nN);
    k_fill <<<(nE + tb - 1) / tb, tb>>>(ei, nE);

    // layer 1: H = fp16(x @ W1)   (tensor cores)
    k_gemm1<<<(nN + 63) / 64, 256>>>(x, W1, nN);
    // hidden = fp16(relu(A_hat @ H + b1))
    k_gather0<<<(nN * 16 + tb - 1) / tb, tb>>>(b1, nN);
    // out = relu((A_hat @ hidden) @ [W2|W3] + bias)   (tensor cores)
    k_gather_gemm2<<<(nN + 63) / 64, 256>>>(W2, W3, b2, b3, out, nN);
}

// round 12
// speedup vs baseline: 2.9339x; 1.0317x over previous
#include <cuda_runtime.h>
#include <cuda_fp16.h>

#define MAX_NODES 50000
#define MAX_EDGES 800000
#define CH 128
#define OUTC 64

// ---- device scratch ----
__device__ __half g_H[MAX_NODES * CH];       // fp16(x @ W1)
__device__ __half g_hidden[MAX_NODES * CH];  // fp16(relu(A_hat@H+b1))
__device__ int    g_deg[MAX_NODES];
__device__ float  g_dinv[MAX_NODES];
// CSR by target node; edge payload {src:int, nrm:float}
__device__ int    g_ptr[MAX_NODES + 1];
__device__ int    g_cursor[MAX_NODES];
__device__ int2   g_edge[MAX_EDGES];
// decoupled-lookback scan state
__device__ int    g_aggval[64];
__device__ int    g_aggflag[64];

// ---------------- mma / ldmatrix macros ----------------
#define LDSM_X4(r0, r1, r2, r3, addr) \
    asm volatile("ldmatrix.sync.aligned.m8n8.x4.shared.b16 {%0,%1,%2,%3}, [%4];" \
                 : "=r"(r0), "=r"(r1), "=r"(r2), "=r"(r3) : "r"(addr))
#define LDSM_X4_T(r0, r1, r2, r3, addr) \
    asm volatile("ldmatrix.sync.aligned.m8n8.x4.trans.shared.b16 {%0,%1,%2,%3}, [%4];" \
                 : "=r"(r0), "=r"(r1), "=r"(r2), "=r"(r3) : "r"(addr))
#define MMA16816(c0, c1, c2, c3, a0, a1, a2, a3, b0, b1) \
    asm volatile("mma.sync.aligned.m16n8k16.row.col.f32.f16.f16.f32 " \
                 "{%0,%1,%2,%3}, {%4,%5,%6,%7}, {%8,%9}, {%0,%1,%2,%3};" \
                 : "+f"(c0), "+f"(c1), "+f"(c2), "+f"(c3) \
                 : "r"(a0), "r"(a1), "r"(a2), "r"(a3), "r"(b0), "r"(b1))

// XOR swizzle for 256B rows (128 halves): conflict-free ldmatrix.
__device__ __forceinline__ int swz(int row, int colh) {
    int chunk = colh >> 3;
    chunk = (chunk & 8) | ((chunk ^ row) & 7);
    return row * 128 + chunk * 8 + (colh & 7);
}

// Per-block int64-vs-int32 edge dtype detection (odd words all zero => int64).
__device__ __forceinline__ int detect_is64(const void* ei) {
    __shared__ int s_is64;
    if (threadIdx.x < 32) {
        int w = ((const int*)ei)[2 * threadIdx.x + 1];
        unsigned m = __ballot_sync(~0u, w == 0);
        if (threadIdx.x == 0) s_is64 = (m == ~0u);
    }
    __syncthreads();
    return s_is64;
}

__device__ __forceinline__ int edge_at(const void* ei, int i, int is64) {
    if (is64) return (int)((const long long*)ei)[i];
    return ((const int*)ei)[i];
}

// ---------------- zero degrees + scan state ----------------
__global__ void k_zero(int n) {
    int i = blockIdx.x * blockDim.x + threadIdx.x;
    if (i < n) g_deg[i] = 0;
    if (i < 64) { g_aggflag[i] = 0; g_aggval[i] = 0; }
}

__global__ void k_count(const void* __restrict__ ei, int nE) {
    int is64 = detect_is64(ei);
    int e = blockIdx.x * blockDim.x + threadIdx.x;
    if (e < nE) atomicAdd(&g_deg[edge_at(ei, nE + e, is64)], 1);
}

// ---------------- single-pass scan (decoupled lookback, <=64 blocks) ----------------
// Also fuses dinv computation and cursor init.
__global__ __launch_bounds__(1024) void k_scan(int n) {
    __shared__ int wsum[32];
    __shared__ int s_off;
    int b = blockIdx.x;
    int i = b * 1024 + threadIdx.x;
    int lane = threadIdx.x & 31, wid = threadIdx.x >> 5;
    int d = (i < n) ? g_deg[i] : 0;
    if (i < n) g_dinv[i] = rsqrtf((float)(d + 1));   // +1 self loop
    int s = d;
#pragma unroll
    for (int o = 1; o < 32; o <<= 1) {
        int t = __shfl_up_sync(~0u, s, o);
        if (lane >= o) s += t;
    }
    if (lane == 31) wsum[wid] = s;
    __syncthreads();
    if (wid == 0) {
        int ws = wsum[lane];
#pragma unroll
        for (int o = 1; o < 32; o <<= 1) {
            int t = __shfl_up_sync(~0u, ws, o);
            if (lane >= o) ws += t;
        }
        wsum[lane] = ws;
    }
    __syncthreads();
    int incl = s + (wid > 0 ? wsum[wid - 1] : 0);

    // publish block aggregate
    if (threadIdx.x == 1023) {
        g_aggval[b] = incl;
        __threadfence();
        atomicExch(&g_aggflag[b], 1);
    }
    // lane-parallel lookback over predecessors (grid <= 64 blocks, all resident)
    if (threadIdx.x < 32) {
        int acc = 0;
        for (int p = lane; p < b; p += 32) {
            while (atomicAdd(&g_aggflag[p], 0) == 0) {}
            acc += atomicAdd(&g_aggval[p], 0);
        }
#pragma unroll
        for (int o = 16; o; o >>= 1) acc += __shfl_down_sync(~0u, acc, o);
        if (lane == 0) s_off = acc;
    }
    __syncthreads();
    if (i < n) {
        int p1 = incl + s_off;
        g_ptr[i + 1] = p1;
        g_cursor[i] = p1 - d;
    }
    if (i == 0) g_ptr[0] = 0;
}

__global__ void k_fill(const void* __restrict__ ei, int nE) {
    int is64 = detect_is64(ei);
    int e = blockIdx.x * blockDim.x + threadIdx.x;
    if (e < nE) {
        int r = edge_at(ei, e, is64);
        int c = edge_at(ei, nE + e, is64);
        int pos = atomicAdd(&g_cursor[c], 1);
        g_edge[pos] = make_int2(r, __float_as_int(g_dinv[r] * g_dinv[c]));
    }
}

// ---------------- fp32x8 -> swizzled fp16 smem store ----------------
__device__ __forceinline__ void st_chunk_h(__half* S, int row, int chunk,
                                           float4 u, float4 v) {
    int4 pk;
    ((__half2*)&pk)[0] = __floats2half2_rn(u.x, u.y);
    ((__half2*)&pk)[1] = __floats2half2_rn(u.z, u.w);
    ((__half2*)&pk)[2] = __floats2half2_rn(v.x, v.y);
    ((__half2*)&pk)[3] = __floats2half2_rn(v.z, v.w);
    *(int4*)&S[swz(row, chunk * 8)] = pk;
}

// ---------------- mma mainloop: C[8][4] += As(64x128) @ Wh(128x128) ----------------
__device__ __forceinline__ void mma_tile(const __half* As, const __half* Wh,
                                         float C[8][4], int wr, int wc, int lane) {
    unsigned a_base = (unsigned)__cvta_generic_to_shared(As);
    unsigned w_base = (unsigned)__cvta_generic_to_shared(Wh);
#pragma unroll
    for (int ks = 0; ks < 8; ks++) {
        unsigned r0, r1, r2, r3;
        int arow = wr * 16 + (lane & 15);
        int acolh = ks * 16 + ((lane >> 4) << 3);
        unsigned a0, a1, a2, a3;
        LDSM_X4(a0, a1, a2, a3, a_base + swz(arow, acolh) * 2);
#pragma unroll
        for (int f2 = 0; f2 < 4; f2++) {
            int brow = ks * 16 + (lane & 15);
            int bcolh = wc * 64 + f2 * 16 + (((lane >> 4) & 1) << 3);
            LDSM_X4_T(r0, r1, r2, r3, w_base + swz(brow, bcolh) * 2);
            MMA16816(C[f2 * 2][0], C[f2 * 2][1], C[f2 * 2][2], C[f2 * 2][3],
                     a0, a1, a2, a3, r0, r1);
            MMA16816(C[f2 * 2 + 1][0], C[f2 * 2 + 1][1], C[f2 * 2 + 1][2], C[f2 * 2 + 1][3],
                     a0, a1, a2, a3, r2, r3);
        }
    }
}

// ---------------- GEMM layer 1: g_H = fp16(x @ W1)  (HMMA) ----------------
__global__ __launch_bounds__(256) void k_gemm1(const float* __restrict__ X,
                                               const float* __restrict__ W, int n) {
    __shared__ __half As[64 * 128];   // 16 KB
    __shared__ __half Wh[128 * 128];  // 32 KB
    int tid = threadIdx.x;
    int row0 = blockIdx.x * 64;

#pragma unroll
    for (int j = 0; j < 8; j++) {
        int task = tid + j * 256;
        int k = task >> 4, ch = task & 15;
        float4 u = *(const float4*)&W[(size_t)k * 128 + ch * 8];
        float4 v = *(const float4*)&W[(size_t)k * 128 + ch * 8 + 4];
        st_chunk_h(Wh, k, ch, u, v);
    }
#pragma unroll
    for (int j = 0; j < 4; j++) {
        int task = tid + j * 256;
        int r = task >> 4, ch = task & 15;
        float4 u = make_float4(0.f, 0.f, 0.f, 0.f), v = u;
        if (row0 + r < n) {
            u = *(const float4*)&X[(size_t)(row0 + r) * 128 + ch * 8];
            v = *(const float4*)&X[(size_t)(row0 + r) * 128 + ch * 8 + 4];
        }
        st_chunk_h(As, r, ch, u, v);
    }
    __syncthreads();

    int lane = tid & 31, wid = tid >> 5;
    int wr = wid >> 1, wc = wid & 1;
    float C[8][4];
#pragma unroll
    for (int f = 0; f < 8; f++)
#pragma unroll
        for (int q = 0; q < 4; q++) C[f][q] = 0.f;

    mma_tile(As, Wh, C, wr, wc, lane);

    int g = lane >> 2, t = lane & 3;
#pragma unroll
    for (int f = 0; f < 8; f++) {
        int col = wc * 64 + f * 8 + t * 2;
        int row = row0 + wr * 16 + g;
        if (row < n)
            *(__half2*)&g_H[(size_t)row * 128 + col] = __floats2half2_rn(C[f][0], C[f][1]);
        if (row + 8 < n)
            *(__half2*)&g_H[(size_t)(row + 8) * 128 + col] = __floats2half2_rn(C[f][2], C[f][3]);
    }
}

// ---------------- fp16-row gather (16 lanes per node, 8 ch per lane) ----------------
__device__ __forceinline__ void cvt8(int4 raw, float o[8]) {
    const __half2* h = (const __half2*)&raw;
    float2 a = __half22float2(h[0]), b = __half22float2(h[1]);
    float2 c = __half22float2(h[2]), d = __half22float2(h[3]);
    o[0] = a.x; o[1] = a.y; o[2] = b.x; o[3] = b.y;
    o[4] = c.x; o[5] = c.y; o[6] = d.x; o[7] = d.y;
}

__device__ __forceinline__ void gather_row_h(const __half* __restrict__ Hh,
                                             int node, int l, float f[8]) {
    float dn = g_dinv[node];
    float s0 = dn * dn;
    int4 raw = *(const int4*)(Hh + (size_t)node * CH + l * 8);
    float t[8]; cvt8(raw, t);
#pragma unroll
    for (int k = 0; k < 8; k++) f[k] = t[k] * s0;   // self loop

    int beg = g_ptr[node], end = g_ptr[node + 1];
    int j = beg;
    for (; j + 4 <= end; j += 4) {
        int2 p0 = g_edge[j], p1 = g_edge[j + 1], p2 = g_edge[j + 2], p3 = g_edge[j + 3];
        int4 r0 = *(const int4*)(Hh + (size_t)p0.x * CH + l * 8);
        int4 r1 = *(const int4*)(Hh + (size_t)p1.x * CH + l * 8);
        int4 r2 = *(const int4*)(Hh + (size_t)p2.x * CH + l * 8);
        int4 r3 = *(const int4*)(Hh + (size_t)p3.x * CH + l * 8);
        float w0 = __int_as_float(p0.y), w1 = __int_as_float(p1.y);
        float w2 = __int_as_float(p2.y), w3 = __int_as_float(p3.y);
        float t0[8], t1[8], t2[8], t3[8];
        cvt8(r0, t0); cvt8(r1, t1); cvt8(r2, t2); cvt8(r3, t3);
#pragma unroll
        for (int k = 0; k < 8; k++)
            f[k] += t0[k] * w0 + t1[k] * w1 + t2[k] * w2 + t3[k] * w3;
    }
    for (; j < end; j++) {
        int2 p = g_edge[j];
        int4 r = *(const int4*)(Hh + (size_t)p.x * CH + l * 8);
        float w = __int_as_float(p.y);
        float t0[8]; cvt8(r, t0);
#pragma unroll
        for (int k = 0; k < 8; k++) f[k] += t0[k] * w;
    }
}

// ---------------- gather pass 1: hidden = fp16(relu(A_hat @ H + b1)) ----------------
__global__ __launch_bounds__(256) void k_gather0(const float* __restrict__ b1, int n) {
    int gt = blockIdx.x * 256 + threadIdx.x;
    int node = gt >> 4, l = gt & 15;
    if (node >= n) return;
    float f[8];
    gather_row_h(g_H, node, l, f);
    float4 ba = *(const float4*)&b1[l * 8];
    float4 bb = *(const float4*)&b1[l * 8 + 4];
    f[0] = fmaxf(f[0] + ba.x, 0.f); f[1] = fmaxf(f[1] + ba.y, 0.f);
    f[2] = fmaxf(f[2] + ba.z, 0.f); f[3] = fmaxf(f[3] + ba.w, 0.f);
    f[4] = fmaxf(f[4] + bb.x, 0.f); f[5] = fmaxf(f[5] + bb.y, 0.f);
    f[6] = fmaxf(f[6] + bb.z, 0.f); f[7] = fmaxf(f[7] + bb.w, 0.f);
    int4 pk;
    ((__half2*)&pk)[0] = __floats2half2_rn(f[0], f[1]);
    ((__half2*)&pk)[1] = __floats2half2_rn(f[2], f[3]);
    ((__half2*)&pk)[2] = __floats2half2_rn(f[4], f[5]);
    ((__half2*)&pk)[3] = __floats2half2_rn(f[6], f[7]);
    *(int4*)&g_hidden[(size_t)node * CH + l * 8] = pk;
}

// ---------------- fused: As = fp16(A_hat @ hidden), HMMA, relu+bias, split ----------------
__global__ __launch_bounds__(256) void k_gather_gemm2(const float* __restrict__ W2,
                                                      const float* __restrict__ W3,
                                                      const float* __restrict__ b2,
                                                      const float* __restrict__ b3,
                                                      float* __restrict__ out, int n) {
    __shared__ __half As[64 * 128];   // 16 KB
    __shared__ __half Wh[128 * 128];  // 32 KB: [W2 | W3]
    int tid = threadIdx.x;
    int node0 = blockIdx.x * 64;

#pragma unroll
    for (int j = 0; j < 8; j++) {
        int task = tid + j * 256;
        int k = task >> 4, ch = task & 15;
        const float* src = (ch < 8) ? &W2[(size_t)k * OUTC + ch * 8]
                                    : &W3[(size_t)k * OUTC + (ch - 8) * 8];
        float4 u = *(const float4*)&src[0];
        float4 v = *(const float4*)&src[4];
        st_chunk_h(Wh, k, ch, u, v);
    }

    int gg = tid >> 4, l = tid & 15;
#pragma unroll 1
    for (int i = 0; i < 4; i++) {
        int nl = gg * 4 + i;
        int node = node0 + nl;
        float f[8] = {0.f, 0.f, 0.f, 0.f, 0.f, 0.f, 0.f, 0.f};
        if (node < n) gather_row_h(g_hidden, node, l, f);
        st_chunk_h(As, nl, l,
                   make_float4(f[0], f[1], f[2], f[3]),
                   make_float4(f[4], f[5], f[6], f[7]));
    }
    __syncthreads();

    int lane = tid & 31, wid = tid >> 5;
    int wr = wid >> 1, wc = wid & 1;
    float C[8][4];
#pragma unroll
    for (int f = 0; f < 8; f++)
#pragma unroll
        for (int q = 0; q < 4; q++) C[f][q] = 0.f;

    mma_tile(As, Wh, C, wr, wc, lane);

    const float* bb = wc ? b3 : b2;
    float* ob = wc ? out + (size_t)n * OUTC : out;
    int g = lane >> 2, t = lane & 3;
#pragma unroll
    for (int f = 0; f < 8; f++) {
        int col = f * 8 + t * 2;
        float bx = bb[col], by = bb[col + 1];
        int row = node0 + wr * 16 + g;
        if (row < n) {
            float2 v = make_float2(fmaxf(C[f][0] + bx, 0.f), fmaxf(C[f][1] + by, 0.f));
            *(float2*)&ob[(size_t)row * OUTC + col] = v;
        }
        if (row + 8 < n) {
            float2 v = make_float2(fmaxf(C[f][2] + bx, 0.f), fmaxf(C[f][3] + by, 0.f));
            *(float2*)&ob[(size_t)(row + 8) * OUTC + col] = v;
        }
    }
}

extern "C" void kernel_launch(void* const* d_in, const int* in_sizes, int n_in,
                              void* d_out, int out_size) {
    const float* x  = (const float*)d_in[0];
    const void*  ei = d_in[1];
    const float* W1 = (const float*)d_in[2];
    const float* b1 = (const float*)d_in[3];
    const float* W2 = (const float*)d_in[4];
    const float* b2 = (const float*)d_in[5];
    const float* W3 = (const float*)d_in[6];
    const float* b3 = (const float*)d_in[7];
    float* out = (float*)d_out;

    int nN = in_sizes[0] / CH;   // 50000
    int nE = in_sizes[1] / 2;    // 800000
    int tb = 256;
    int nb = (nN + 1023) / 1024;

    // one-time side-stream infra (created on the uncaptured correctness call;
    // identical launch sequence on every call)
    static cudaStream_t s2 = nullptr;
    static cudaEvent_t evFork = nullptr, evJoin = nullptr;
    if (s2 == nullptr) {
        cudaStreamCreateWithFlags(&s2, cudaStreamNonBlocking);
        cudaEventCreateWithFlags(&evFork, cudaEventDisableTiming);
        cudaEventCreateWithFlags(&evJoin, cudaEventDisableTiming);
    }

    // fork: gemm1 (independent of CSR) on side stream
    cudaEventRecord(evFork, 0);
    cudaStreamWaitEvent(s2, evFork, 0);
    k_gemm1<<<(nN + 63) / 64, 256, 0, s2>>>(x, W1, nN);
    cudaEventRecord(evJoin, s2);

    // main stream: CSR build
    k_zero <<<(nN + tb - 1) / tb, tb>>>(nN);
    k_count<<<(nE + tb - 1) / tb, tb>>>(ei, nE);
    k_scan <<<nb, 1024>>>(nN);
    k_fill <<<(nE + tb - 1) / tb, tb>>>(ei, nE);

    // join, then the dependent chain
    cudaStreamWaitEvent(0, evJoin, 0);
    k_gather0<<<(nN * 16 + tb - 1) / tb, tb>>>(b1, nN);
    k_gather_gemm2<<<(nN + 63) / 64, 256>>>(W2, W3, b2, b3, out, nN);
}